// round 17
// baseline (speedup 1.0000x reference)
#include <cuda_runtime.h>
#include <cstdint>

// FinePreprocess: gather 5x5 windows (stride 4, pad 2) from two NCHW f32
// feature maps at per-match window indices. Output = concat[(M,25,C) f0,
// (M,25,C) f1]; per-match flat layout is c*25 + wy*5 + wx.
//
// R15 (resubmitted after infra failure): 4 adjacent patches per block.
//   - 8 independent gather LDG.128s per thread issued before ONE barrier
//     (per-SM in-flight loads: 1280 thr x 8 = 10240 vs R12's 7680),
//   - patches 4k..4k+3 are output-adjacent -> one contiguous 3200-float4
//     span, exactly 5 coalesced STG.cs.128 per thread,
//   - quarter the barrier count of R8. smem 51.2KB -> 2 blocks/SM.

#define FP_N 4
#define FP_C 128
#define FP_H 240
#define FP_W 320
#define FP_OUTW 80
#define FP_L 4800            // 60*80
#define PATCH_WORDS 3200     // C*25
#define PPB 4
#define BLOCK_VEC4 (PPB * 800)   // 3200 float4

__device__ __forceinline__ void stcs4(float4* p, float4 v)
{
    asm volatile("st.global.cs.v4.f32 [%0], {%1,%2,%3,%4};"
                 :: "l"(p), "f"(v.x), "f"(v.y), "f"(v.z), "f"(v.w)
                 : "memory");
}

__device__ __forceinline__ void gather_row(
    int p, int M, int wy, int c,
    const float* __restrict__ feat0, const float* __restrict__ feat1,
    const int* __restrict__ b_ids, const int* __restrict__ i_ids,
    const int* __restrict__ j_ids,
    float4& A, float4& B)
{
    int f = p >= M;
    int m = f ? p - M : p;

    int b   = min(max(b_ids[m], 0), FP_N - 1);        // block-uniform, L1 bcast
    int idx = min(max((f ? j_ids : i_ids)[m], 0), FP_L - 1);
    int gy  = idx / FP_OUTW;
    int gx  = idx - gy * FP_OUTW;
    int h   = gy * 4 + wy - 2;

    A = make_float4(0.f, 0.f, 0.f, 0.f);
    B = make_float4(0.f, 0.f, 0.f, 0.f);
    if (h >= 0 && h < FP_H) {
        const float* __restrict__ src = f ? feat1 : feat0;
        const float4* __restrict__ row4 = (const float4*)
            (src + (((long long)b * FP_C + c) * FP_H + h) * FP_W);
        if (gx > 0)                      // block-uniform branch
            A = __ldg(row4 + (gx - 1));  // elements 4gx-4 .. 4gx-1
        B = __ldg(row4 + gx);            // elements 4gx   .. 4gx+3
    }
    // window = elements 4gx-2 .. 4gx+2  ->  {A.z, A.w, B.x, B.y, B.z}
}

__global__ void __launch_bounds__(640, 2)
fine_gather_kernel(const float* __restrict__ feat0,
                   const float* __restrict__ feat1,
                   const int* __restrict__ b_ids,
                   const int* __restrict__ i_ids,
                   const int* __restrict__ j_ids,
                   float* __restrict__ out,
                   int M)
{
    __shared__ float s[PPB * PATCH_WORDS];   // 4 patches, output order

    int tid = threadIdx.x;            // 0..639 == c*5 + wy
    int c   = tid / 5;
    int wy  = tid - 5 * c;
    int p0  = blockIdx.x * PPB;       // 2M % 4 == 0 for M=6000

    // issue all gathers up front: 8 independent LDG.128 in flight per thread
    float4 A0, B0, A1, B1, A2, B2, A3, B3;
    gather_row(p0,     M, wy, c, feat0, feat1, b_ids, i_ids, j_ids, A0, B0);
    gather_row(p0 + 1, M, wy, c, feat0, feat1, b_ids, i_ids, j_ids, A1, B1);
    gather_row(p0 + 2, M, wy, c, feat0, feat1, b_ids, i_ids, j_ids, A2, B2);
    gather_row(p0 + 3, M, wy, c, feat0, feat1, b_ids, i_ids, j_ids, A3, B3);

    float* __restrict__ sr = s + tid * 5;
    sr[0] = A0.z; sr[1] = A0.w; sr[2] = B0.x; sr[3] = B0.y; sr[4] = B0.z;
    sr += PATCH_WORDS;
    sr[0] = A1.z; sr[1] = A1.w; sr[2] = B1.x; sr[3] = B1.y; sr[4] = B1.z;
    sr += PATCH_WORDS;
    sr[0] = A2.z; sr[1] = A2.w; sr[2] = B2.x; sr[3] = B2.y; sr[4] = B2.z;
    sr += PATCH_WORDS;
    sr[0] = A3.z; sr[1] = A3.w; sr[2] = B3.x; sr[3] = B3.y; sr[4] = B3.z;

    __syncthreads();

    // fused writeout: 3200 consecutive float4 covering all 4 patches
    float4* __restrict__ out4 = (float4*)out + (long long)p0 * 800;
    const float4* __restrict__ s4 = (const float4*)s;
#pragma unroll
    for (int i = 0; i < 5; i++)
        stcs4(out4 + i * 640 + tid, s4[i * 640 + tid]);
}

extern "C" void kernel_launch(void* const* d_in, const int* in_sizes, int n_in,
                              void* d_out, int out_size)
{
    // metadata order: feat_f0, feat_f1, hw0_f, hw0_c, b_ids, i_ids, j_ids
    const float* feat0 = (const float*)d_in[0];
    const float* feat1 = (const float*)d_in[1];
    const int*   b_ids = (const int*)d_in[4];
    const int*   i_ids = (const int*)d_in[5];
    const int*   j_ids = (const int*)d_in[6];
    float* out = (float*)d_out;

    int M = in_sizes[4];   // 6000; 2M divisible by 4

    int blocks = (2 * M) / PPB;
    fine_gather_kernel<<<blocks, 640>>>(feat0, feat1, b_ids, i_ids, j_ids, out, M);
}